// round 3
// baseline (speedup 1.0000x reference)
#include <cuda_runtime.h>

#define DD    32
#define PREV  64
#define HIDN  128
#define HDIM  64
#define NW    ((DD + 1) * PREV)   // 2112
#define BATCH 8192
#define MSTR  36                  // smem row stride (floats): 144B, 16B-aligned, conflict-free

typedef unsigned long long u64;

__device__ __forceinline__ u64 fma2(u64 a, u64 b, u64 c) {
    u64 d; asm("fma.rn.f32x2 %0,%1,%2,%3;" : "=l"(d) : "l"(a), "l"(b), "l"(c)); return d;
}
__device__ __forceinline__ u64 add2(u64 a, u64 b) {
    u64 d; asm("add.rn.f32x2 %0,%1,%2;" : "=l"(d) : "l"(a), "l"(b)); return d;
}
__device__ __forceinline__ u64 pack2(float lo, float hi) {
    u64 r; asm("mov.b64 %0,{%1,%2};" : "=l"(r) : "f"(lo), "f"(hi)); return r;
}
__device__ __forceinline__ float2 unpack2(u64 v) {
    float lo, hi; asm("mov.b64 {%0,%1},%2;" : "=f"(lo), "=f"(hi) : "l"(v));
    return make_float2(lo, hi);
}

// Batch-independent precomputed tensors.
__device__ float g_M[HIDN * DD];   // [h][d]  M = bw @ w1^T
__device__ float g_beff[HIDN];

// ---------------------------------------------------------------------------
// prep: 17 CTAs x 256 threads, fully parallel (no inter-CTA deps).
//  CTA b < 16: w1 rows d in {2b, 2b+1} (128 hyper-rows, warp-per-row),
//              then M[h, 2b + (tid&1)] for all h.
//  CTA 16:     b1 (64 hyper-rows) then beff[h] = bb[h] + bw[h,:].b1
// ---------------------------------------------------------------------------
__global__ void __launch_bounds__(256)
prep_kernel(const float* __restrict__ t,   const float* __restrict__ hw1,
            const float* __restrict__ hb1, const float* __restrict__ hw2,
            const float* __restrict__ hb2, const float* __restrict__ bw,
            const float* __restrict__ bb) {
    __shared__ float hcode[HDIM];
    __shared__ float w1s[2][66];        // padded: conflict-free 2-addr reads
    __shared__ float b1s[PREV];
    __shared__ float bws[HIDN * 65];    // bw padded [h][p] stride 65

    int tid = threadIdx.x, lane = tid & 31, wrp = tid >> 5;
    if (tid < HDIM)
        hcode[tid] = tanhf(t[0] * hw1[tid] + hb1[tid]);
    // stage bw (32KB) into padded smem
    for (int i = tid; i < HIDN * PREV; i += 256)
        bws[(i >> 6) * 65 + (i & 63)] = bw[i];
    __syncthreads();

    int cta = blockIdx.x;
    if (cta < 16) {
        int rbase = cta * 128;          // weight rows for d = 2*cta .. 2*cta+1
#pragma unroll
        for (int rr = wrp; rr < 128; rr += 8) {
            int r = rbase + rr;
            const float* row = hw2 + r * HDIM;
            float acc = hcode[lane] * row[lane] + hcode[lane + 32] * row[lane + 32];
#pragma unroll
            for (int m = 16; m >= 1; m >>= 1)
                acc += __shfl_xor_sync(0xffffffffu, acc, m);
            if (lane == 0) w1s[rr >> 6][rr & 63] = acc + hb2[r];
        }
        __syncthreads();
        int dl = tid & 1, h = tid >> 1;
        int d  = 2 * cta + dl;
        float m = 0.f;
#pragma unroll
        for (int p = 0; p < PREV; p++)
            m += bws[h * 65 + p] * w1s[dl][p];
        g_M[h * DD + d] = m;
    } else {
#pragma unroll
        for (int rr = wrp; rr < PREV; rr += 8) {
            int r = DD * PREV + rr;
            const float* row = hw2 + r * HDIM;
            float acc = hcode[lane] * row[lane] + hcode[lane + 32] * row[lane + 32];
#pragma unroll
            for (int m = 16; m >= 1; m >>= 1)
                acc += __shfl_xor_sync(0xffffffffu, acc, m);
            if (lane == 0) b1s[rr] = acc + hb2[r];
        }
        __syncthreads();
        if (tid < HIDN) {
            float be = bb[tid];
#pragma unroll
            for (int p = 0; p < PREV; p++)
                be += bws[tid * 65 + p] * b1s[p];
            g_beff[tid] = be;
        }
    }
}

// ---------------------------------------------------------------------------
// main: 256 CTAs x 256 threads = 32 rows x 8 h-groups.
// Packed f32x2 FMA throughout; c[h] computed in-CTA from smem.
// ---------------------------------------------------------------------------
__global__ void __launch_bounds__(256)
ode_main_kernel(const float* __restrict__ y,
                const float* __restrict__ w2,
                const float* __restrict__ b2,
                float* __restrict__ out) {
    __shared__ __align__(16) float Mt [HIDN * MSTR];
    __shared__ __align__(16) float W2t[HIDN * MSTR];
    __shared__ float beff[HIDN];
    __shared__ float cs[HIDN];
    __shared__ float b2s[DD];
    __shared__ __align__(16) float xs[32 * 33];

    int tid = threadIdx.x;
    for (int i = tid; i < HIDN * DD; i += 256)
        Mt[(i >> 5) * MSTR + (i & 31)] = g_M[i];           // h-major coalesced
    for (int i = tid; i < HIDN * DD; i += 256) {
        int d = i >> 7, h = i & 127;                        // w2 is [d][h]
        W2t[h * MSTR + d] = w2[i];
    }
    if (tid < HIDN) beff[tid] = g_beff[tid];
    if (tid < DD)   b2s[tid]  = b2[tid];

    int rowbase = blockIdx.x * 32;
    {   // 32 rows x 33 cols = 264 float4, coalesced
        const float4* ysrc = reinterpret_cast<const float4*>(y + rowbase * 33);
        float4* xdst = reinterpret_cast<float4*>(xs);
        for (int i = tid; i < 264; i += 256) xdst[i] = ysrc[i];
    }
    __syncthreads();

    // c[h] = sum_d M[h,d] * w2t[h,d]  (redundant per CTA, 16 MAC/thread)
    if (tid < HIDN) {
        float c = 0.f;
#pragma unroll
        for (int d = 0; d < DD; d++)
            c += Mt[tid * MSTR + d] * W2t[tid * MSTR + d];
        cs[tid] = c;
    }
    __syncthreads();

    int g  = tid & 7;     // h-group
    int rl = tid >> 3;    // local row 0..31

    u64 xp[16];
#pragma unroll
    for (int j = 0; j < 16; j++)
        xp[j] = pack2(xs[rl * 33 + 2 * j], xs[rl * 33 + 2 * j + 1]);

    u64 dxp[16];
#pragma unroll
    for (int j = 0; j < 16; j++) dxp[j] = 0ull;
    float dv = 0.f;

#pragma unroll 4
    for (int hh = 0; hh < 16; hh++) {
        int col = hh * 8 + g;
        const ulonglong2* mrow = reinterpret_cast<const ulonglong2*>(Mt + col * MSTR);
        u64 sp0 = 0ull, sp1 = 0ull;
#pragma unroll
        for (int k = 0; k < 8; k++) {
            ulonglong2 mv = mrow[k];
            sp0 = fma2(mv.x, xp[2 * k],     sp0);
            sp1 = fma2(mv.y, xp[2 * k + 1], sp1);
        }
        float2 sv = unpack2(add2(sp0, sp1));
        float s = sv.x + sv.y + beff[col];
        float ex = __expf(2.f * s);
        float r  = __fdividef(2.f, ex + 1.f);
        float a  = 1.f - r;                 // tanh(s)
        dv += r * (2.f - r) * cs[col];      // (1 - a^2) * c
        u64 aa = pack2(a, a);
        const ulonglong2* wrow = reinterpret_cast<const ulonglong2*>(W2t + col * MSTR);
#pragma unroll
        for (int k = 0; k < 8; k++) {
            ulonglong2 wv = wrow[k];
            dxp[2 * k]     = fma2(wv.x, aa, dxp[2 * k]);
            dxp[2 * k + 1] = fma2(wv.y, aa, dxp[2 * k + 1]);
        }
    }

    // reduce across the 8 h-groups (lanes differ in g bits 0..2)
#pragma unroll
    for (int m = 1; m <= 4; m <<= 1) {
        dv += __shfl_xor_sync(0xffffffffu, dv, m);
#pragma unroll
        for (int j = 0; j < 16; j++)
            dxp[j] = add2(dxp[j], __shfl_xor_sync(0xffffffffu, dxp[j], m));
    }

    __syncthreads();   // all xp reads of xs are done; reuse xs as output tile
    if (g == 0) {
#pragma unroll
        for (int j = 0; j < 16; j++) {
            float2 v = unpack2(dxp[j]);
            xs[rl * 33 + 2 * j]     = v.x + b2s[2 * j];
            xs[rl * 33 + 2 * j + 1] = v.y + b2s[2 * j + 1];
        }
        xs[rl * 33 + 32] = -dv;
    }
    __syncthreads();
    {   // coalesced vector store of the 32x33 tile
        const float4* src = reinterpret_cast<const float4*>(xs);
        float4* dst = reinterpret_cast<float4*>(out + rowbase * 33);
        for (int i = tid; i < 264; i += 256) dst[i] = src[i];
    }
}

// ---------------------------------------------------------------------------
// inputs: 0:y 1:t 2:hw1 3:hb1 4:hw2 5:hb2 6:bw 7:bb 8:w2 9:b2
// ---------------------------------------------------------------------------
extern "C" void kernel_launch(void* const* d_in, const int* in_sizes, int n_in,
                              void* d_out, int out_size) {
    const float* y   = (const float*)d_in[0];
    const float* t   = (const float*)d_in[1];
    const float* hw1 = (const float*)d_in[2];
    const float* hb1 = (const float*)d_in[3];
    const float* hw2 = (const float*)d_in[4];
    const float* hb2 = (const float*)d_in[5];
    const float* bw  = (const float*)d_in[6];
    const float* bb  = (const float*)d_in[7];
    const float* w2  = (const float*)d_in[8];
    const float* b2  = (const float*)d_in[9];
    float* out = (float*)d_out;

    prep_kernel<<<17, 256>>>(t, hw1, hb1, hw2, hb2, bw, bb);
    ode_main_kernel<<<BATCH / 32, 256>>>(y, w2, b2, out);
}

// round 4
// speedup vs baseline: 1.0795x; 1.0795x over previous
#include <cuda_runtime.h>

#define DD    32
#define PREV  64
#define HIDN  128
#define HDIM  64
#define NW    ((DD + 1) * PREV)   // 2112
#define BATCH 8192
#define RSTR  36   // smem row stride (floats); d0..15 @ +0, d16..31 @ +18, beff @ +34, c @ +35

typedef unsigned long long u64;

__device__ __forceinline__ u64 fma2(u64 a, u64 b, u64 c) {
    u64 d; asm("fma.rn.f32x2 %0,%1,%2,%3;" : "=l"(d) : "l"(a), "l"(b), "l"(c)); return d;
}
__device__ __forceinline__ u64 add2(u64 a, u64 b) {
    u64 d; asm("add.rn.f32x2 %0,%1,%2;" : "=l"(d) : "l"(a), "l"(b)); return d;
}
__device__ __forceinline__ u64 pack2(float lo, float hi) {
    u64 r; asm("mov.b64 %0,{%1,%2};" : "=l"(r) : "f"(lo), "f"(hi)); return r;
}
__device__ __forceinline__ float2 unpack2(u64 v) {
    float lo, hi; asm("mov.b64 {%0,%1},%2;" : "=f"(lo), "=f"(hi) : "l"(v));
    return make_float2(lo, hi);
}

// Batch-independent precomputed tensors.
__device__ float g_M[HIDN * DD];    // [h][d]  M = bw @ w1^T
__device__ float g_w2t[HIDN * DD];  // [h][d]  w2^T
__device__ float g_beff[HIDN];

// ---------------------------------------------------------------------------
// prep: 18 CTAs x 256 threads, fully parallel.
//  CTA b<16 : w1 rows for d in {2b,2b+1}, then M[:, those d]
//  CTA 16   : b1, then beff = bb + bw.b1
//  CTA 17   : transpose w2 [d][h] -> g_w2t [h][d]
// ---------------------------------------------------------------------------
__global__ void __launch_bounds__(256)
prep_kernel(const float* __restrict__ t,   const float* __restrict__ hw1,
            const float* __restrict__ hb1, const float* __restrict__ hw2,
            const float* __restrict__ hb2, const float* __restrict__ bw,
            const float* __restrict__ bb,  const float* __restrict__ w2) {
    __shared__ float hcode[HDIM];
    __shared__ float w1s[2][66];
    __shared__ float b1s[PREV];
    __shared__ float bws[HIDN * 65];

    int tid = threadIdx.x, lane = tid & 31, wrp = tid >> 5;
    int cta = blockIdx.x;

    if (cta == 17) {   // pure transpose, no staging needed
        for (int i = tid; i < HIDN * DD; i += 256) {
            int d = i >> 7, h = i & 127;
            g_w2t[h * DD + d] = w2[i];
        }
        return;
    }

    if (tid < HDIM)
        hcode[tid] = tanhf(t[0] * hw1[tid] + hb1[tid]);
    for (int i = tid; i < HIDN * PREV; i += 256)
        bws[(i >> 6) * 65 + (i & 63)] = bw[i];
    __syncthreads();

    if (cta < 16) {
        int rbase = cta * 128;
#pragma unroll
        for (int rr = wrp; rr < 128; rr += 8) {
            int r = rbase + rr;
            const float* row = hw2 + r * HDIM;
            float acc = hcode[lane] * row[lane] + hcode[lane + 32] * row[lane + 32];
#pragma unroll
            for (int m = 16; m >= 1; m >>= 1)
                acc += __shfl_xor_sync(0xffffffffu, acc, m);
            if (lane == 0) w1s[rr >> 6][rr & 63] = acc + hb2[r];
        }
        __syncthreads();
        int dl = tid & 1, h = tid >> 1;
        int d  = 2 * cta + dl;
        float m = 0.f;
#pragma unroll
        for (int p = 0; p < PREV; p++)
            m += bws[h * 65 + p] * w1s[dl][p];
        g_M[h * DD + d] = m;
    } else {
#pragma unroll
        for (int rr = wrp; rr < PREV; rr += 8) {
            int r = DD * PREV + rr;
            const float* row = hw2 + r * HDIM;
            float acc = hcode[lane] * row[lane] + hcode[lane + 32] * row[lane + 32];
#pragma unroll
            for (int m = 16; m >= 1; m >>= 1)
                acc += __shfl_xor_sync(0xffffffffu, acc, m);
            if (lane == 0) b1s[rr] = acc + hb2[r];
        }
        __syncthreads();
        if (tid < HIDN) {
            float be = bb[tid];
#pragma unroll
            for (int p = 0; p < PREV; p++)
                be += bws[tid * 65 + p] * b1s[p];
            g_beff[tid] = be;
        }
    }
}

// ---------------------------------------------------------------------------
// main: 512 CTAs x 256 threads, 16 rows/CTA.
// thread = (g2 = tid&7: h-group of 16 h) x (dh = bit3: d-half) x (rw = tid>>4: row)
// d-split halves per-thread register state -> 3 CTAs/SM, 24 warps/SM.
// LDS.64 layout: dh0 banks ≡{0,1} mod 4, dh1 ≡{2,3} mod 4 -> conflict-free.
// ---------------------------------------------------------------------------
__global__ void __launch_bounds__(256, 3)
ode_main_kernel(const float* __restrict__ y,
                const float* __restrict__ b2,
                float* __restrict__ out) {
    __shared__ __align__(16) float Mt [HIDN * RSTR];
    __shared__ __align__(16) float W2t[HIDN * RSTR];
    __shared__ __align__(16) float xs [16 * RSTR];   // input tile; reused as output tile
    __shared__ float b2s[DD];

    int tid = threadIdx.x;

    // fill Mt / W2t d-regions (d -> d + 2*(d>=16) within each 36-float row)
    {
        const float4* ms = reinterpret_cast<const float4*>(g_M);
        const float4* ws = reinterpret_cast<const float4*>(g_w2t);
        for (int i = tid; i < HIDN * DD / 4; i += 256) {
            int col = i >> 3, q = i & 7;
            int off = col * RSTR + ((q < 4) ? 4 * q : 4 * q + 2);
            float4 mv = ms[i], wv = ws[i];
            *reinterpret_cast<float2*>(Mt  + off)     = make_float2(mv.x, mv.y);
            *reinterpret_cast<float2*>(Mt  + off + 2) = make_float2(mv.z, mv.w);
            *reinterpret_cast<float2*>(W2t + off)     = make_float2(wv.x, wv.y);
            *reinterpret_cast<float2*>(W2t + off + 2) = make_float2(wv.z, wv.w);
        }
    }
    if (tid < HIDN) Mt[tid * RSTR + 34] = g_beff[tid];
    if (tid < DD)   b2s[tid] = b2[tid];

    int rowbase = blockIdx.x * 16;
    for (int i = tid; i < 16 * 33; i += 256) {
        int r = i / 33, c = i - r * 33;
        xs[r * RSTR + c] = y[rowbase * 33 + i];
    }
    __syncthreads();

    // c[h] = sum_d M[h,d]*w2t[h,d]  -> Mt[h*RSTR+35]
    if (tid < HIDN) {
        const float* mr = Mt  + tid * RSTR;
        const float* wr = W2t + tid * RSTR;
        float c = 0.f;
#pragma unroll
        for (int k = 0; k < 16; k++) c += mr[k] * wr[k];
#pragma unroll
        for (int k = 18; k < 34; k++) c += mr[k] * wr[k];
        Mt[tid * RSTR + 35] = c;
    }
    __syncthreads();

    int g2 = tid & 7;
    int dh = (tid >> 3) & 1;
    int rw = tid >> 4;
    int moff = dh * 18;

    u64 xp[8];
    {
        const float* xrow = xs + rw * RSTR + dh * 16;
#pragma unroll
        for (int j = 0; j < 8; j++)
            xp[j] = *reinterpret_cast<const u64*>(xrow + 2 * j);
    }

    u64 dxp[8];
#pragma unroll
    for (int j = 0; j < 8; j++) dxp[j] = 0ull;
    float dv = 0.f;

#pragma unroll 4
    for (int hh = 0; hh < 16; hh++) {
        int col = hh * 8 + g2;
        const u64* mr = reinterpret_cast<const u64*>(Mt + col * RSTR + moff);
        u64 a0 = fma2(mr[0], xp[0], 0ull);
        u64 a1 = fma2(mr[1], xp[1], 0ull);
        u64 a2 = fma2(mr[2], xp[2], 0ull);
        u64 a3 = fma2(mr[3], xp[3], 0ull);
        a0 = fma2(mr[4], xp[4], a0);
        a1 = fma2(mr[5], xp[5], a1);
        a2 = fma2(mr[6], xp[6], a2);
        a3 = fma2(mr[7], xp[7], a3);
        float2 sv = unpack2(add2(add2(a0, a1), add2(a2, a3)));
        float sh = sv.x + sv.y;
        sh += __shfl_xor_sync(0xffffffffu, sh, 8);      // merge d-halves
        float s  = sh + Mt[col * RSTR + 34];
        float ex = __expf(2.f * s);
        float r  = __fdividef(2.f, ex + 1.f);
        float a  = 1.f - r;                              // tanh(s)
        if (dh == 0)
            dv += r * (2.f - r) * Mt[col * RSTR + 35];   // (1-a^2)*c
        u64 aa = pack2(a, a);
        const u64* wr = reinterpret_cast<const u64*>(W2t + col * RSTR + moff);
#pragma unroll
        for (int j = 0; j < 8; j++)
            dxp[j] = fma2(wr[j], aa, dxp[j]);
    }

    // reduce over the 8 g2 groups (bits 0..2); dh stays separate (owns its d-half)
#pragma unroll
    for (int m = 1; m <= 4; m <<= 1) {
        dv += __shfl_xor_sync(0xffffffffu, dv, m);
#pragma unroll
        for (int j = 0; j < 8; j++)
            dxp[j] = add2(dxp[j], __shfl_xor_sync(0xffffffffu, dxp[j], m));
    }

    __syncthreads();   // all xs input reads finished; reuse xs as output tile
    if (g2 == 0) {
        float* orow = xs + rw * RSTR + dh * 16;
#pragma unroll
        for (int j = 0; j < 8; j++) {
            float2 v = unpack2(dxp[j]);
            orow[2 * j]     = v.x + b2s[dh * 16 + 2 * j];
            orow[2 * j + 1] = v.y + b2s[dh * 16 + 2 * j + 1];
        }
        if (dh == 0) xs[rw * RSTR + 32] = -dv;
    }
    __syncthreads();
    for (int i = tid; i < 16 * 33; i += 256) {
        int r = i / 33, c = i - r * 33;
        out[rowbase * 33 + i] = xs[r * RSTR + c];
    }
}

// ---------------------------------------------------------------------------
// inputs: 0:y 1:t 2:hw1 3:hb1 4:hw2 5:hb2 6:bw 7:bb 8:w2 9:b2
// ---------------------------------------------------------------------------
extern "C" void kernel_launch(void* const* d_in, const int* in_sizes, int n_in,
                              void* d_out, int out_size) {
    const float* y   = (const float*)d_in[0];
    const float* t   = (const float*)d_in[1];
    const float* hw1 = (const float*)d_in[2];
    const float* hb1 = (const float*)d_in[3];
    const float* hw2 = (const float*)d_in[4];
    const float* hb2 = (const float*)d_in[5];
    const float* bw  = (const float*)d_in[6];
    const float* bb  = (const float*)d_in[7];
    const float* w2  = (const float*)d_in[8];
    const float* b2  = (const float*)d_in[9];
    float* out = (float*)d_out;

    prep_kernel<<<18, 256>>>(t, hw1, hb1, hw2, hb2, bw, bb, w2);
    ode_main_kernel<<<BATCH / 16, 256>>>(y, b2, out);
}

// round 5
// speedup vs baseline: 1.3297x; 1.2317x over previous
#include <cuda_runtime.h>

#define DD    32
#define PREV  64
#define HIDN  128
#define HDIM  64
#define NW    ((DD + 1) * PREV)   // 2112
#define BATCH 8192
#define RSTR  36   // smem row stride (floats); d0..15 @ +0, d16..31 @ +18, beff @ +34, c @ +35

typedef unsigned long long u64;

__device__ __forceinline__ u64 fma2(u64 a, u64 b, u64 c) {
    u64 d; asm("fma.rn.f32x2 %0,%1,%2,%3;" : "=l"(d) : "l"(a), "l"(b), "l"(c)); return d;
}
__device__ __forceinline__ u64 add2(u64 a, u64 b) {
    u64 d; asm("add.rn.f32x2 %0,%1,%2;" : "=l"(d) : "l"(a), "l"(b)); return d;
}
__device__ __forceinline__ u64 pack2(float lo, float hi) {
    u64 r; asm("mov.b64 %0,{%1,%2};" : "=l"(r) : "f"(lo), "f"(hi)); return r;
}
__device__ __forceinline__ float2 unpack2(u64 v) {
    float lo, hi; asm("mov.b64 {%0,%1},%2;" : "=f"(lo), "=f"(hi) : "l"(v));
    return make_float2(lo, hi);
}

// Batch-independent precomputed tensors.
__device__ float g_M[HIDN * DD];    // [h][d]  M = bw @ w1^T
__device__ float g_w2t[HIDN * DD];  // [h][d]  w2^T
__device__ float g_beff[HIDN];

// ---------------------------------------------------------------------------
// prep: 18 CTAs x 256 threads, fully parallel.
// ---------------------------------------------------------------------------
__global__ void __launch_bounds__(256)
prep_kernel(const float* __restrict__ t,   const float* __restrict__ hw1,
            const float* __restrict__ hb1, const float* __restrict__ hw2,
            const float* __restrict__ hb2, const float* __restrict__ bw,
            const float* __restrict__ bb,  const float* __restrict__ w2) {
    __shared__ float hcode[HDIM];
    __shared__ float w1s[2][66];
    __shared__ float b1s[PREV];
    __shared__ float bws[HIDN * 65];

    int tid = threadIdx.x, lane = tid & 31, wrp = tid >> 5;
    int cta = blockIdx.x;

    if (cta == 17) {   // transpose w2 [d][h] -> [h][d]
        for (int i = tid; i < HIDN * DD; i += 256) {
            int d = i >> 7, h = i & 127;
            g_w2t[h * DD + d] = w2[i];
        }
        return;
    }

    if (tid < HDIM)
        hcode[tid] = tanhf(t[0] * hw1[tid] + hb1[tid]);
    for (int i = tid; i < HIDN * PREV; i += 256)
        bws[(i >> 6) * 65 + (i & 63)] = bw[i];
    __syncthreads();

    if (cta < 16) {
        int rbase = cta * 128;
#pragma unroll
        for (int rr = wrp; rr < 128; rr += 8) {
            int r = rbase + rr;
            const float* row = hw2 + r * HDIM;
            float acc = hcode[lane] * row[lane] + hcode[lane + 32] * row[lane + 32];
#pragma unroll
            for (int m = 16; m >= 1; m >>= 1)
                acc += __shfl_xor_sync(0xffffffffu, acc, m);
            if (lane == 0) w1s[rr >> 6][rr & 63] = acc + hb2[r];
        }
        __syncthreads();
        int dl = tid & 1, h = tid >> 1;
        int d  = 2 * cta + dl;
        float m = 0.f;
#pragma unroll
        for (int p = 0; p < PREV; p++)
            m += bws[h * 65 + p] * w1s[dl][p];
        g_M[h * DD + d] = m;
    } else {
#pragma unroll
        for (int rr = wrp; rr < PREV; rr += 8) {
            int r = DD * PREV + rr;
            const float* row = hw2 + r * HDIM;
            float acc = hcode[lane] * row[lane] + hcode[lane + 32] * row[lane + 32];
#pragma unroll
            for (int m = 16; m >= 1; m >>= 1)
                acc += __shfl_xor_sync(0xffffffffu, acc, m);
            if (lane == 0) b1s[rr] = acc + hb2[r];
        }
        __syncthreads();
        if (tid < HIDN) {
            float be = bb[tid];
#pragma unroll
            for (int p = 0; p < PREV; p++)
                be += bws[tid * 65 + p] * b1s[p];
            g_beff[tid] = be;
        }
    }
}

// ---------------------------------------------------------------------------
// main: 256 CTAs x 256 threads, 32 rows/CTA, TWO rows per thread.
// thread = (g2 = tid&7) x (dh = bit3) x (rw = tid>>4, rows 2rw & 2rw+1)
// Each weight LDS.64 feeds two independent row-chains (2x ILP),
// weight smem traffic per row halves vs round 4.
// ---------------------------------------------------------------------------
__global__ void __launch_bounds__(256, 2)
ode_main_kernel(const float* __restrict__ y,
                const float* __restrict__ b2,
                float* __restrict__ out) {
    __shared__ __align__(16) float Mt [HIDN * RSTR];
    __shared__ __align__(16) float W2t[HIDN * RSTR];
    __shared__ __align__(16) float xs [32 * RSTR];   // input tile; reused as output tile
    __shared__ float b2s[DD];

    int tid = threadIdx.x;

    // fill Mt / W2t d-regions (d -> d + 2*(d>=16) within each 36-float row)
    {
        const float4* ms = reinterpret_cast<const float4*>(g_M);
        const float4* ws = reinterpret_cast<const float4*>(g_w2t);
        for (int i = tid; i < HIDN * DD / 4; i += 256) {
            int col = i >> 3, q = i & 7;
            int off = col * RSTR + ((q < 4) ? 4 * q : 4 * q + 2);
            float4 mv = ms[i], wv = ws[i];
            *reinterpret_cast<float2*>(Mt  + off)     = make_float2(mv.x, mv.y);
            *reinterpret_cast<float2*>(Mt  + off + 2) = make_float2(mv.z, mv.w);
            *reinterpret_cast<float2*>(W2t + off)     = make_float2(wv.x, wv.y);
            *reinterpret_cast<float2*>(W2t + off + 2) = make_float2(wv.z, wv.w);
        }
    }
    if (tid < HIDN) Mt[tid * RSTR + 34] = g_beff[tid];
    if (tid < DD)   b2s[tid] = b2[tid];

    int rowbase = blockIdx.x * 32;
    for (int i = tid; i < 32 * 33; i += 256) {
        int r = i / 33, c = i - r * 33;
        xs[r * RSTR + c] = y[rowbase * 33 + i];
    }
    __syncthreads();

    // c[h] = sum_d M[h,d]*w2t[h,d]  -> Mt[h*RSTR+35]
    if (tid < HIDN) {
        const float* mr = Mt  + tid * RSTR;
        const float* wr = W2t + tid * RSTR;
        float c = 0.f;
#pragma unroll
        for (int k = 0; k < 16; k++) c += mr[k] * wr[k];
#pragma unroll
        for (int k = 18; k < 34; k++) c += mr[k] * wr[k];
        Mt[tid * RSTR + 35] = c;
    }
    __syncthreads();

    int g2 = tid & 7;
    int dh = (tid >> 3) & 1;
    int rw = tid >> 4;          // 0..15 -> rows 2rw, 2rw+1
    int moff = dh * 18;

    u64 xp0[8], xp1[8];
    {
        const float* xr0 = xs + (2 * rw)     * RSTR + dh * 16;
        const float* xr1 = xs + (2 * rw + 1) * RSTR + dh * 16;
#pragma unroll
        for (int j = 0; j < 8; j++) {
            xp0[j] = *reinterpret_cast<const u64*>(xr0 + 2 * j);
            xp1[j] = *reinterpret_cast<const u64*>(xr1 + 2 * j);
        }
    }

    u64 dxp0[8], dxp1[8];
#pragma unroll
    for (int j = 0; j < 8; j++) { dxp0[j] = 0ull; dxp1[j] = 0ull; }
    float dv0 = 0.f, dv1 = 0.f;

#pragma unroll 2
    for (int hh = 0; hh < 16; hh++) {
        int col = hh * 8 + g2;
        const u64* mr = reinterpret_cast<const u64*>(Mt + col * RSTR + moff);
        u64 a0 = 0ull, a1 = 0ull, b0 = 0ull, b1 = 0ull;
#pragma unroll
        for (int j = 0; j < 8; j += 2) {
            u64 m0 = mr[j], m1 = mr[j + 1];
            a0 = fma2(m0, xp0[j],     a0);
            a1 = fma2(m1, xp0[j + 1], a1);
            b0 = fma2(m0, xp1[j],     b0);
            b1 = fma2(m1, xp1[j + 1], b1);
        }
        float2 svA = unpack2(add2(a0, a1));
        float2 svB = unpack2(add2(b0, b1));
        u64 sp = pack2(svA.x + svA.y, svB.x + svB.y);
        sp = add2(sp, __shfl_xor_sync(0xffffffffu, sp, 8));  // merge d-halves (both rows)
        float2 sv = unpack2(sp);
        float be = Mt[col * RSTR + 34];
        float s0 = sv.x + be, s1 = sv.y + be;

        float r0 = __fdividef(2.f, __expf(2.f * s0) + 1.f);
        float r1 = __fdividef(2.f, __expf(2.f * s1) + 1.f);
        float av0 = 1.f - r0, av1 = 1.f - r1;     // tanh
        if (dh == 0) {
            float cc = Mt[col * RSTR + 35];
            dv0 += r0 * (2.f - r0) * cc;
            dv1 += r1 * (2.f - r1) * cc;
        }
        u64 aa0 = pack2(av0, av0), aa1 = pack2(av1, av1);
        const u64* wr = reinterpret_cast<const u64*>(W2t + col * RSTR + moff);
#pragma unroll
        for (int j = 0; j < 8; j++) {
            u64 wv = wr[j];
            dxp0[j] = fma2(wv, aa0, dxp0[j]);
            dxp1[j] = fma2(wv, aa1, dxp1[j]);
        }
    }

    // reduce over the 8 g2 groups (lane bits 0..2)
#pragma unroll
    for (int m = 1; m <= 4; m <<= 1) {
        u64 dvp = pack2(dv0, dv1);
        dvp = add2(dvp, __shfl_xor_sync(0xffffffffu, dvp, m));
        float2 dvv = unpack2(dvp);
        dv0 = dvv.x; dv1 = dvv.y;
#pragma unroll
        for (int j = 0; j < 8; j++) {
            dxp0[j] = add2(dxp0[j], __shfl_xor_sync(0xffffffffu, dxp0[j], m));
            dxp1[j] = add2(dxp1[j], __shfl_xor_sync(0xffffffffu, dxp1[j], m));
        }
    }

    __syncthreads();   // all xs input reads done; reuse xs as output tile
    if (g2 == 0) {
        float* o0 = xs + (2 * rw)     * RSTR + dh * 16;
        float* o1 = xs + (2 * rw + 1) * RSTR + dh * 16;
#pragma unroll
        for (int j = 0; j < 8; j++) {
            float2 v0 = unpack2(dxp0[j]);
            float2 v1 = unpack2(dxp1[j]);
            float bl = b2s[dh * 16 + 2 * j], bh = b2s[dh * 16 + 2 * j + 1];
            o0[2 * j] = v0.x + bl;  o0[2 * j + 1] = v0.y + bh;
            o1[2 * j] = v1.x + bl;  o1[2 * j + 1] = v1.y + bh;
        }
        if (dh == 0) {
            xs[(2 * rw)     * RSTR + 32] = -dv0;
            xs[(2 * rw + 1) * RSTR + 32] = -dv1;
        }
    }
    __syncthreads();
    for (int i = tid; i < 32 * 33; i += 256) {
        int r = i / 33, c = i - r * 33;
        out[rowbase * 33 + i] = xs[r * RSTR + c];
    }
}

// ---------------------------------------------------------------------------
// inputs: 0:y 1:t 2:hw1 3:hb1 4:hw2 5:hb2 6:bw 7:bb 8:w2 9:b2
// ---------------------------------------------------------------------------
extern "C" void kernel_launch(void* const* d_in, const int* in_sizes, int n_in,
                              void* d_out, int out_size) {
    const float* y   = (const float*)d_in[0];
    const float* t   = (const float*)d_in[1];
    const float* hw1 = (const float*)d_in[2];
    const float* hb1 = (const float*)d_in[3];
    const float* hw2 = (const float*)d_in[4];
    const float* hb2 = (const float*)d_in[5];
    const float* bw  = (const float*)d_in[6];
    const float* bb  = (const float*)d_in[7];
    const float* w2  = (const float*)d_in[8];
    const float* b2  = (const float*)d_in[9];
    float* out = (float*)d_out;

    prep_kernel<<<18, 256>>>(t, hw1, hb1, hw2, hb2, bw, bb, w2);
    ode_main_kernel<<<BATCH / 32, 256>>>(y, b2, out);
}